// round 2
// baseline (speedup 1.0000x reference)
#include <cuda_runtime.h>

// Problem shape (fixed by reference): B=256 students, T=200 steps, Q=1000 questions.
#define NB 256
#define NT 200
#define NQ 1000
#define TM1 (NT - 1)   // 199

// Scratch (no cudaMalloc allowed).
__device__ float        g_student_loss[NB];
__device__ unsigned int g_arrive = 0;   // self-resetting arrival counter

__device__ __forceinline__ float bce_term(float p, float a) {
    // torch BCELoss: -(a*log(p) + (1-a)*log(1-p)), logs clamped at -100
    float logp   = fmaxf(logf(p), -100.0f);
    float log1mp = fmaxf(log1pf(-p), -100.0f);
    return -(a * logp + (1.0f - a) * log1mp);
}

__global__ __launch_bounds__(256)
void fused_loss_kernel(const float* __restrict__ logit_c,
                       const float* __restrict__ logit_t,
                       const int*   __restrict__ q_idx,
                       const int*   __restrict__ correct,
                       float*       __restrict__ out) {
    const int b    = blockIdx.x;    // student
    const int t    = threadIdx.x;   // step 0..TM1-1 (threads >= TM1 idle)
    const int lane = t & 31;
    const int warp = t >> 5;

    __shared__ int   s_i[8];
    __shared__ float s_f[8];
    __shared__ int   s_last;
    __shared__ int   s_is_last_block;

    float pc = 0.0f, pt = 0.0f, a = 0.0f;
    const bool active = (t < TM1);

    if (active) {
        // q used at step t comes from q_idx[b, t+1]
        const int  q    = q_idx[b * NT + t + 1];
        const long base = ((long)b * NT + t) * NQ;
        const float lc = __ldg(&logit_c[base + q]);
        const float lt = __ldg(&logit_t[base + q]);
        pc = 1.0f / (1.0f + expf(-lc));
        pt = 1.0f / (1.0f + expf(-lt));
        a  = (float)correct[b * NT + t + 1];
        out[1 + b * TM1 + t]            = 0.5f * (pt + pc);  // p_mean
        out[1 + NB * TM1 + b * TM1 + t] = a;                 // ground_truth
    }

    // ---- reduction 1: last index with pc > 0 (reference's dynamic trim) ----
    int idx = (active && pc > 0.0f) ? t : -1;
    #pragma unroll
    for (int o = 16; o; o >>= 1) idx = max(idx, __shfl_xor_sync(0xffffffffu, idx, o));
    if (lane == 0) s_i[warp] = idx;
    __syncthreads();
    if (t == 0) {
        int m = s_i[0];
        #pragma unroll
        for (int i = 1; i < 8; i++) m = max(m, s_i[i]);
        s_last = (m < 0) ? (TM1 - 1) : m;   // all-invalid -> full mask (matches ref)
    }
    __syncthreads();
    const int   last  = s_last;
    const float count = (float)(last + 1);

    // ---- masked BCE sum over the block ----
    float e = 0.0f;
    if (active && t <= last) e = bce_term(pt, a) + bce_term(pc, a);
    #pragma unroll
    for (int o = 16; o; o >>= 1) e += __shfl_xor_sync(0xffffffffu, e, o);
    if (lane == 0) s_f[warp] = e;
    __syncthreads();
    if (t == 0) {
        float s = 0.0f;
        #pragma unroll
        for (int i = 0; i < 8; i++) s += s_f[i];
        g_student_loss[b] = s / count;
        __threadfence();                      // make loss visible before arrival
        unsigned ticket = atomicAdd(&g_arrive, 1u);
        s_is_last_block = (ticket == NB - 1);
    }
    __syncthreads();

    // ---- last-arriving block performs the deterministic final sum ----
    if (s_is_last_block) {
        // Fixed read order -> bitwise-identical result regardless of which
        // block finishes last.
        float v = __ldcg(&g_student_loss[t]);   // NB == 256 == blockDim
        #pragma unroll
        for (int o = 16; o; o >>= 1) v += __shfl_xor_sync(0xffffffffu, v, o);
        if (lane == 0) s_f[warp] = v;
        __syncthreads();
        if (t == 0) {
            float s = 0.0f;
            #pragma unroll
            for (int i = 0; i < 8; i++) s += s_f[i];
            out[0]   = s;
            g_arrive = 0;   // reset for next graph replay
        }
    }
}

extern "C" void kernel_launch(void* const* d_in, const int* in_sizes, int n_in,
                              void* d_out, int out_size) {
    const float* logit_c = (const float*)d_in[0];
    const float* logit_t = (const float*)d_in[1];
    const int*   q_idx   = (const int*)d_in[2];
    const int*   correct = (const int*)d_in[3];
    float* out = (float*)d_out;

    fused_loss_kernel<<<NB, 256>>>(logit_c, logit_t, q_idx, correct, out);
}

// round 9
// speedup vs baseline: 1.0257x; 1.0257x over previous
#include <cuda_runtime.h>

// Problem shape (fixed by reference): B=256 students, T=200 steps, Q=1000 questions.
#define NB 256
#define NT 200
#define NQ 1000
#define TM1 (NT - 1)   // 199

// Scratch (no cudaMalloc allowed).
__device__ float g_student_loss[NB];

// BCE(sigmoid(x), a) = softplus(x) - a*x, softplus via stable form.
// Reference's -100 log-clamps never fire for |x| < 88 (inputs are randn).
__device__ __forceinline__ float bce_from_logit(float x, float a) {
    float sp = fmaxf(x, 0.0f) + __logf(1.0f + __expf(-fabsf(x)));
    return sp - a * x;
}

__global__ __launch_bounds__(256)
void per_student_kernel(const float* __restrict__ logit_c,
                        const float* __restrict__ logit_t,
                        const int*   __restrict__ q_idx,
                        const int*   __restrict__ correct,
                        float*       __restrict__ out) {
    const int b    = blockIdx.x;    // student
    const int t    = threadIdx.x;   // step 0..TM1-1 (threads >= TM1 idle)
    const int lane = t & 31;
    const int warp = t >> 5;

    __shared__ int   s_i[8];
    __shared__ float s_f[8];
    __shared__ float s_e[256];      // raw per-step losses (slow-path only)

    float e = 0.0f, pc = 0.0f;
    int   idx = -1;
    const bool active = (t < TM1);

    if (active) {
        const int   q    = q_idx[b * NT + t + 1];
        const float a    = (float)correct[b * NT + t + 1];
        const long  base = ((long)b * NT + t) * NQ;
        const float xc = __ldg(&logit_c[base + q]);
        const float xt = __ldg(&logit_t[base + q]);
        pc = 1.0f / (1.0f + __expf(-xc));
        const float pt = 1.0f / (1.0f + __expf(-xt));
        out[1 + b * TM1 + t]            = 0.5f * (pt + pc);  // p_mean
        out[1 + NB * TM1 + b * TM1 + t] = a;                 // ground_truth
        e   = bce_from_logit(xc, a) + bce_from_logit(xt, a);
        idx = (pc > 0.0f) ? t : -1;                          // reference trim
    }
    s_e[t] = e;

    // ---- single fused reduction: max(idx) and sum(e) together ----
    float se = e;
    #pragma unroll
    for (int o = 16; o; o >>= 1) {
        se  += __shfl_xor_sync(0xffffffffu, se, o);
        idx  = max(idx, __shfl_xor_sync(0xffffffffu, idx, o));
    }
    if (lane == 0) { s_f[warp] = se; s_i[warp] = idx; }
    __syncthreads();

    if (t == 0) {
        int   last = s_i[0];
        float sum  = s_f[0];
        #pragma unroll
        for (int i = 1; i < 8; i++) { last = max(last, s_i[i]); sum += s_f[i]; }
        if (last < 0) last = TM1 - 1;             // all-invalid -> full mask (ref)
        if (last != TM1 - 1) {                    // trim actually trims: recompute
            sum = 0.0f;
            for (int j = 0; j <= last; j++) sum += s_e[j];
        }
        g_student_loss[b] = sum / (float)(last + 1);
    }
}

__global__ __launch_bounds__(256)
void final_loss_kernel(float* __restrict__ out) {
    const int t    = threadIdx.x;
    const int lane = t & 31;
    const int warp = t >> 5;
    __shared__ float s_f[8];

    float v = g_student_loss[t];   // NB == 256 == blockDim, fixed order
    #pragma unroll
    for (int o = 16; o; o >>= 1) v += __shfl_xor_sync(0xffffffffu, v, o);
    if (lane == 0) s_f[warp] = v;
    __syncthreads();
    if (t == 0) {
        float s = 0.0f;
        #pragma unroll
        for (int i = 0; i < 8; i++) s += s_f[i];
        out[0] = s;
    }
}

extern "C" void kernel_launch(void* const* d_in, const int* in_sizes, int n_in,
                              void* d_out, int out_size) {
    const float* logit_c = (const float*)d_in[0];
    const float* logit_t = (const float*)d_in[1];
    const int*   q_idx   = (const int*)d_in[2];
    const int*   correct = (const int*)d_in[3];
    float* out = (float*)d_out;

    per_student_kernel<<<NB, 256>>>(logit_c, logit_t, q_idx, correct, out);
    final_loss_kernel<<<1, 256>>>(out);
}